// round 12
// baseline (speedup 1.0000x reference)
#include <cuda_runtime.h>
#include <math.h>

#define BB 256
#define TT 128
#define FF 128
#define HH 512
#define BT (BB*TT)   // 32768

// ---------------- persistent scratch (device globals; no allocation) ----------------
__device__ float g_h[BB*HH];          // hidden state (held in DECAYED form during a step)
__device__ float g_c[BB*HH];          // cell state
__device__ float g_xh_acc[BB*FF];     // split-K accumulator for x_hist (zeroed-after-read)
__device__ float g_z_acc[BB*FF];      // split-K accumulator for z_h
__device__ float g_xhist[BB*FF];      // x_hist (with bias)
__device__ float g_xc[BB*FF];         // x_c
__device__ float g_gates[BB*4*HH];    // LSTM pre-activations
__device__ float g_gh[BT*HH];         // precomputed gamma_h for all (b,t)  (64 MB)
__device__ float g_gx[BT*FF];         // precomputed gamma_x                (16 MB)
__device__ float g_alpha[BT*FF];      // precomputed alpha                  (16 MB)
__device__ float g_denom[TT];
__device__ float g_loss;

// ---------------- helpers ----------------
__device__ __forceinline__ float block_sum256(float v) {
    __shared__ float red[256];
    int tid = threadIdx.x;
    red[tid] = v; __syncthreads();
#pragma unroll
    for (int s = 128; s > 0; s >>= 1) {
        if (tid < s) red[tid] += red[tid + s];
        __syncthreads();
    }
    return red[0];
}

__device__ __forceinline__ float sigmoidf(float x) { return 1.f / (1.f + expf(-x)); }

// Generic register-tiled GEMM tile: C[r,c] = sum_k la(r,k)*lw(c,k), 256 threads.
// BM x BN output tile, BK=16, micro (BM/16) x (BN/16) per thread.
template<int BM, int BN, class LA, class LW, class EP>
__device__ __forceinline__ void gemm_tile(int K, LA la, LW lw, EP ep) {
    constexpr int MI = BM / 16, NI = BN / 16;
    __shared__ float As[BM][17];
    __shared__ float Ws[BN][17];
    const int tid = threadIdx.x;
    const int tx = tid & 15, ty = tid >> 4;
    const int lc = tid & 15, lr = tid >> 4;
    float acc[MI][NI];
#pragma unroll
    for (int i = 0; i < MI; i++)
#pragma unroll
        for (int j = 0; j < NI; j++) acc[i][j] = 0.f;

    for (int k0 = 0; k0 < K; k0 += 16) {
#pragma unroll
        for (int i = 0; i < BM / 16; i++) As[lr + 16 * i][lc] = la(lr + 16 * i, k0 + lc);
#pragma unroll
        for (int i = 0; i < BN / 16; i++) Ws[lr + 16 * i][lc] = lw(lr + 16 * i, k0 + lc);
        __syncthreads();
#pragma unroll
        for (int kk = 0; kk < 16; kk++) {
            float a[MI], w[NI];
#pragma unroll
            for (int i = 0; i < MI; i++) a[i] = As[ty * MI + i][kk];
#pragma unroll
            for (int j = 0; j < NI; j++) w[j] = Ws[tx * NI + j][kk];
#pragma unroll
            for (int i = 0; i < MI; i++)
#pragma unroll
                for (int j = 0; j < NI; j++) acc[i][j] = fmaf(a[i], w[j], acc[i][j]);
        }
        __syncthreads();
    }
#pragma unroll
    for (int i = 0; i < MI; i++)
#pragma unroll
        for (int j = 0; j < NI; j++) ep(ty * MI + i, tx * NI + j, acc[i][j]);
}

// ---------------- setup kernels ----------------
__global__ void k_init() {
    int i = blockIdx.x * 256 + threadIdx.x;   // grid covers BB*HH
    g_h[i] = 0.f; g_c[i] = 0.f;
    if (i < BB * FF) { g_xh_acc[i] = 0.f; g_z_acc[i] = 0.f; }
    if (i == 0) g_loss = 0.f;
}

__global__ void k_denom(const float* __restrict__ ev) {
    int t = blockIdx.x;
    float s = 0.f;
    for (int i = threadIdx.x; i < BB * FF; i += 256) {
        int b = i >> 7, f = i & 127;
        s += ev[(b * TT + t) * FF + f];
    }
    float tot = block_sum256(s);
    if (threadIdx.x == 0) g_denom[t] = tot + 1e-8f;
}

// gamma_x = exp(-relu(d * diag(td_x_W) + td_x_b)), elementwise over [BT,F]
__global__ void k_gammax(const float* __restrict__ d, const float* __restrict__ tdxW,
                         const float* __restrict__ tdxb) {
    int i = blockIdx.x * 256 + threadIdx.x;
    if (i >= BT * FF) return;
    int f = i & 127;
    float v = d[i] * tdxW[f * FF + f] + tdxb[f];
    g_gx[i] = expf(-fmaxf(v, 0.f));
}

// gamma_h for all (b,t): [BT,H] = exp(-relu(d @ td_h_W^T + b))
__global__ __launch_bounds__(256) void k_gammah(const float* __restrict__ d,
        const float* __restrict__ W, const float* __restrict__ bias) {
    int r0 = blockIdx.y * 64, j0 = blockIdx.x * 64;
    gemm_tile<64, 64>(FF,
        [&](int r, int k) { return d[(r0 + r) * FF + k]; },
        [&](int r, int k) { return W[(j0 + r) * FF + k]; },
        [&](int r, int c, float acc) {
            float v = acc + bias[j0 + c];
            g_gh[(r0 + r) * HH + j0 + c] = expf(-fmaxf(v, 0.f));
        });
}

// alpha for all (b,t): sigmoid([gamma_x, m] @ wc_W^T + wc_b)
__global__ __launch_bounds__(256) void k_alpha(const float* __restrict__ m,
        const float* __restrict__ wcW, const float* __restrict__ wcb) {
    int r0 = blockIdx.y * 64, j0 = blockIdx.x * 64;
    gemm_tile<64, 64>(2 * FF,
        [&](int r, int k) {
            int row = r0 + r;
            return (k < FF) ? g_gx[row * FF + k] : m[row * FF + (k - FF)];
        },
        [&](int r, int k) { return wcW[(j0 + r) * (2 * FF) + k]; },
        [&](int r, int c, float acc) {
            g_alpha[(r0 + r) * FF + j0 + c] = sigmoidf(acc + wcb[j0 + c]);
        });
}

// ---------------- per-step kernels ----------------
// K2a: x_hist partials = h @ hist_W^T, split-K (4 chunks of 128) -> atomic into g_xh_acc
__global__ __launch_bounds__(256) void k2a(const float* __restrict__ histW) {
    int b0 = blockIdx.y * 64, j0 = blockIdx.x * 64, kb = blockIdx.z * 128;
    gemm_tile<64, 64>(128,
        [&](int r, int k) { return g_h[(b0 + r) * HH + kb + k]; },
        [&](int r, int k) { return histW[(j0 + r) * HH + kb + k]; },
        [&](int r, int c, float acc) { atomicAdd(&g_xh_acc[(b0 + r) * FF + j0 + c], acc); });
}

// K2b: finalize x_hist (+bias), x_c, loss term 1; zero accumulator for next step
__global__ void k2b(int t, const float* __restrict__ x, const float* __restrict__ m,
                    const float* __restrict__ histb, const float* __restrict__ tgt,
                    const float* __restrict__ ev) {
    int i = blockIdx.x * 256 + threadIdx.x;          // exactly BB*FF threads
    int b = i >> 7, f = i & 127;
    int gi = (b * TT + t) * FF + f;
    float s = g_xh_acc[i]; g_xh_acc[i] = 0.f;
    float xh = s + histb[f];
    g_xhist[i] = xh;
    float mt = m[gi];
    g_xc[i] = mt * x[gi] + (1.f - mt) * xh;
    float dv = xh - tgt[gi];
    float tot = block_sum256(dv * dv * ev[gi]);
    if (threadIdx.x == 0) atomicAdd(&g_loss, tot / g_denom[t]);
}

// K3a: z partials = x_c @ feat_W^T (diag handled later), split-K 2x64
__global__ __launch_bounds__(256) void k3a(const float* __restrict__ featW) {
    int b0 = blockIdx.y * 64, j0 = blockIdx.x * 64, kb = blockIdx.z * 64;
    gemm_tile<64, 64>(64,
        [&](int r, int k) { return g_xc[(b0 + r) * FF + kb + k]; },
        [&](int r, int k) { return featW[(j0 + r) * FF + kb + k]; },
        [&](int r, int c, float acc) { atomicAdd(&g_z_acc[(b0 + r) * FF + j0 + c], acc); });
}

// K3b: z (subtract diagonal, +bias), c_h, c_c -> d_out, loss terms 2&3
__global__ void k3b(int t, const float* __restrict__ x, const float* __restrict__ m,
                    const float* __restrict__ featW, const float* __restrict__ featb,
                    const float* __restrict__ tgt, const float* __restrict__ ev,
                    float* __restrict__ out) {
    int i = blockIdx.x * 256 + threadIdx.x;
    int b = i >> 7, f = i & 127;
    int gi = (b * TT + t) * FF + f;
    float zacc = g_z_acc[i]; g_z_acc[i] = 0.f;
    float xc = g_xc[i];
    float z = zacc - xc * featW[f * FF + f] + featb[f];
    float a = g_alpha[gi];
    float xh = g_xhist[i];
    float ch = a * z + (1.f - a) * xh;
    float mt = m[gi];
    out[gi] = mt * x[gi] + (1.f - mt) * ch;     // imputation c_c
    float d1 = z - tgt[gi], d2 = ch - tgt[gi];
    float tot = block_sum256((d1 * d1 + d2 * d2) * ev[gi]);
    if (threadIdx.x == 0) atomicAdd(&g_loss, tot / g_denom[t]);
}

// K4: gates = [c_c, m] @ W_ih^T + h @ W_hh^T + b_ih + b_hh   (K = 768)
__global__ __launch_bounds__(256) void k4(int t, const float* __restrict__ m,
        const float* __restrict__ Wih, const float* __restrict__ Whh,
        const float* __restrict__ bih, const float* __restrict__ bhh,
        const float* __restrict__ cc /* = d_out */) {
    int b0 = blockIdx.y * 64, j0 = blockIdx.x * 32;
    gemm_tile<64, 32>(2 * FF + HH,
        [&](int r, int k) {
            int b = b0 + r;
            if (k < FF)        return cc[(b * TT + t) * FF + k];
            else if (k < 2*FF) return m[(b * TT + t) * FF + (k - FF)];
            else               return g_h[b * HH + (k - 2 * FF)];
        },
        [&](int r, int k) {
            int g = j0 + r;
            return (k < 2 * FF) ? Wih[g * (2 * FF) + k] : Whh[g * HH + (k - 2 * FF)];
        },
        [&](int r, int c, float acc) {
            int g = j0 + c;
            g_gates[(b0 + r) * (4 * HH) + g] = acc + bih[g] + bhh[g];
        });
}

// K5: LSTM cell update; fuse the NEXT step's gamma_h decay into the h write
__global__ void k5(int t) {
    int i = blockIdx.x * 256 + threadIdx.x;   // exactly BB*HH threads
    int b = i >> 9, j = i & 511;
    const float* gr = g_gates + b * (4 * HH);
    float ig = gr[j], fg = gr[HH + j], gg = gr[2 * HH + j], og = gr[3 * HH + j];
    float c = sigmoidf(fg) * g_c[i] + sigmoidf(ig) * tanhf(gg);
    float h = sigmoidf(og) * tanhf(c);
    g_c[i] = c;
    if (t + 1 < TT) h *= g_gh[(b * TT + (t + 1)) * HH + j];
    g_h[i] = h;
}

__global__ void k_final(float* out, int idx) {
    out[idx] = g_loss * (1.0f / TT);
}

// ---------------- launch ----------------
extern "C" void kernel_launch(void* const* d_in, const int* in_sizes, int n_in,
                              void* d_out, int out_size) {
    const float* x     = (const float*)d_in[0];
    const float* m     = (const float*)d_in[1];
    const float* d     = (const float*)d_in[2];
    const float* tgt   = (const float*)d_in[3];
    const float* ev    = (const float*)d_in[4];
    const float* tdhW  = (const float*)d_in[5];
    const float* tdhb  = (const float*)d_in[6];
    const float* tdxW  = (const float*)d_in[7];
    const float* tdxb  = (const float*)d_in[8];
    const float* histW = (const float*)d_in[9];
    const float* histb = (const float*)d_in[10];
    const float* featW = (const float*)d_in[11];
    const float* featb = (const float*)d_in[12];
    const float* wcW   = (const float*)d_in[13];
    const float* wcb   = (const float*)d_in[14];
    const float* Wih   = (const float*)d_in[15];
    const float* Whh   = (const float*)d_in[16];
    const float* bih   = (const float*)d_in[17];
    const float* bhh   = (const float*)d_in[18];
    float* out = (float*)d_out;

    k_init<<<(BB * HH) / 256, 256>>>();
    k_denom<<<TT, 256>>>(ev);
    k_gammax<<<(BT * FF) / 256, 256>>>(d, tdxW, tdxb);
    k_gammah<<<dim3(HH / 64, BT / 64), 256>>>(d, tdhW, tdhb);
    k_alpha<<<dim3(2 * FF / 128, BT / 64), 256>>>(m, wcW, wcb);   // (2, 512)

    for (int t = 0; t < TT; t++) {
        k2a<<<dim3(FF / 64, BB / 64, 4), 256>>>(histW);           // (2,4,4)
        k2b<<<(BB * FF) / 256, 256>>>(t, x, m, histb, tgt, ev);
        k3a<<<dim3(FF / 64, BB / 64, 2), 256>>>(featW);           // (2,4,2)
        k3b<<<(BB * FF) / 256, 256>>>(t, x, m, featW, featb, tgt, ev, out);
        k4<<<dim3(4 * HH / 32, BB / 64), 256>>>(t, m, Wih, Whh, bih, bhh, out); // (64,4)
        k5<<<(BB * HH) / 256, 256>>>(t);
    }

    int lossIdx = BB * TT * FF;
    if (out_size > lossIdx) k_final<<<1, 1>>>(out, lossIdx);
}

// round 13
// speedup vs baseline: 1.0066x; 1.0066x over previous
#include <cuda_runtime.h>
#include <math.h>

#define BB 256
#define TT 128
#define FF 128
#define HH 512
#define BT (BB*TT)   // 32768

// ---------------- persistent scratch (device globals; no allocation) ----------------
__device__ float g_h[BB*HH];          // hidden state (held in DECAYED form during a step)
__device__ float g_c[BB*HH];          // cell state
__device__ float g_xh_acc[BB*FF];     // split-K accumulator for x_hist (zeroed-after-read)
__device__ float g_z_acc[BB*FF];      // split-K accumulator for z_h
__device__ float g_xhist[BB*FF];      // x_hist (with bias)
__device__ float g_xc[BB*FF];         // x_c
__device__ float g_gates[BB*4*HH];    // LSTM pre-activations
__device__ float g_gh[BT*HH];         // precomputed gamma_h for all (b,t)  (64 MB)
__device__ float g_gx[BT*FF];         // precomputed gamma_x                (16 MB)
__device__ float g_alpha[BT*FF];      // precomputed alpha                  (16 MB)
__device__ float g_denom[TT];
__device__ float g_loss;

// ---------------- helpers ----------------
__device__ __forceinline__ float block_sum256(float v) {
    __shared__ float red[256];
    int tid = threadIdx.x;
    red[tid] = v; __syncthreads();
#pragma unroll
    for (int s = 128; s > 0; s >>= 1) {
        if (tid < s) red[tid] += red[tid + s];
        __syncthreads();
    }
    return red[0];
}

__device__ __forceinline__ float sigmoidf(float x) { return 1.f / (1.f + expf(-x)); }

// Generic register-tiled GEMM tile: C[r,c] = sum_k la(r,k)*lw(c,k), 256 threads.
// BM x BN output tile, BK=16, micro (BM/16) x (BN/16) per thread.
template<int BM, int BN, class LA, class LW, class EP>
__device__ __forceinline__ void gemm_tile(int K, LA la, LW lw, EP ep) {
    constexpr int MI = BM / 16, NI = BN / 16;
    __shared__ float As[BM][17];
    __shared__ float Ws[BN][17];
    const int tid = threadIdx.x;
    const int tx = tid & 15, ty = tid >> 4;
    const int lc = tid & 15, lr = tid >> 4;
    float acc[MI][NI];
#pragma unroll
    for (int i = 0; i < MI; i++)
#pragma unroll
        for (int j = 0; j < NI; j++) acc[i][j] = 0.f;

    for (int k0 = 0; k0 < K; k0 += 16) {
#pragma unroll
        for (int i = 0; i < BM / 16; i++) As[lr + 16 * i][lc] = la(lr + 16 * i, k0 + lc);
#pragma unroll
        for (int i = 0; i < BN / 16; i++) Ws[lr + 16 * i][lc] = lw(lr + 16 * i, k0 + lc);
        __syncthreads();
#pragma unroll
        for (int kk = 0; kk < 16; kk++) {
            float a[MI], w[NI];
#pragma unroll
            for (int i = 0; i < MI; i++) a[i] = As[ty * MI + i][kk];
#pragma unroll
            for (int j = 0; j < NI; j++) w[j] = Ws[tx * NI + j][kk];
#pragma unroll
            for (int i = 0; i < MI; i++)
#pragma unroll
                for (int j = 0; j < NI; j++) acc[i][j] = fmaf(a[i], w[j], acc[i][j]);
        }
        __syncthreads();
    }
#pragma unroll
    for (int i = 0; i < MI; i++)
#pragma unroll
        for (int j = 0; j < NI; j++) ep(ty * MI + i, tx * NI + j, acc[i][j]);
}

// ---------------- setup kernels ----------------
__global__ void k_init() {
    int i = blockIdx.x * 256 + threadIdx.x;   // grid covers BB*HH
    g_h[i] = 0.f; g_c[i] = 0.f;
    if (i < BB * FF) { g_xh_acc[i] = 0.f; g_z_acc[i] = 0.f; }
    if (i == 0) g_loss = 0.f;
}

__global__ void k_denom(const float* __restrict__ ev) {
    int t = blockIdx.x;
    float s = 0.f;
    for (int i = threadIdx.x; i < BB * FF; i += 256) {
        int b = i >> 7, f = i & 127;
        s += ev[(b * TT + t) * FF + f];
    }
    float tot = block_sum256(s);
    if (threadIdx.x == 0) g_denom[t] = tot + 1e-8f;
}

// gamma_x = exp(-relu(d * diag(td_x_W) + td_x_b)), elementwise over [BT,F]
__global__ void k_gammax(const float* __restrict__ d, const float* __restrict__ tdxW,
                         const float* __restrict__ tdxb) {
    int i = blockIdx.x * 256 + threadIdx.x;
    if (i >= BT * FF) return;
    int f = i & 127;
    float v = d[i] * tdxW[f * FF + f] + tdxb[f];
    g_gx[i] = expf(-fmaxf(v, 0.f));
}

// gamma_h for all (b,t): [BT,H] = exp(-relu(d @ td_h_W^T + b))
__global__ __launch_bounds__(256) void k_gammah(const float* __restrict__ d,
        const float* __restrict__ W, const float* __restrict__ bias) {
    int r0 = blockIdx.y * 64, j0 = blockIdx.x * 64;
    gemm_tile<64, 64>(FF,
        [&](int r, int k) { return d[(r0 + r) * FF + k]; },
        [&](int r, int k) { return W[(j0 + r) * FF + k]; },
        [&](int r, int c, float acc) {
            float v = acc + bias[j0 + c];
            g_gh[(r0 + r) * HH + j0 + c] = expf(-fmaxf(v, 0.f));
        });
}

// alpha for all (b,t): sigmoid([gamma_x, m] @ wc_W^T + wc_b)
__global__ __launch_bounds__(256) void k_alpha(const float* __restrict__ m,
        const float* __restrict__ wcW, const float* __restrict__ wcb) {
    int r0 = blockIdx.y * 64, j0 = blockIdx.x * 64;
    gemm_tile<64, 64>(2 * FF,
        [&](int r, int k) {
            int row = r0 + r;
            return (k < FF) ? g_gx[row * FF + k] : m[row * FF + (k - FF)];
        },
        [&](int r, int k) { return wcW[(j0 + r) * (2 * FF) + k]; },
        [&](int r, int c, float acc) {
            g_alpha[(r0 + r) * FF + j0 + c] = sigmoidf(acc + wcb[j0 + c]);
        });
}

// ---------------- per-step kernels ----------------
// K2a: x_hist partials = h @ hist_W^T, split-K (4 chunks of 128) -> atomic into g_xh_acc
__global__ __launch_bounds__(256) void k2a(const float* __restrict__ histW) {
    int b0 = blockIdx.y * 64, j0 = blockIdx.x * 64, kb = blockIdx.z * 128;
    gemm_tile<64, 64>(128,
        [&](int r, int k) { return g_h[(b0 + r) * HH + kb + k]; },
        [&](int r, int k) { return histW[(j0 + r) * HH + kb + k]; },
        [&](int r, int c, float acc) { atomicAdd(&g_xh_acc[(b0 + r) * FF + j0 + c], acc); });
}

// K2b: finalize x_hist (+bias), x_c, loss term 1; zero accumulator for next step
__global__ void k2b(int t, const float* __restrict__ x, const float* __restrict__ m,
                    const float* __restrict__ histb, const float* __restrict__ tgt,
                    const float* __restrict__ ev) {
    int i = blockIdx.x * 256 + threadIdx.x;          // exactly BB*FF threads
    int b = i >> 7, f = i & 127;
    int gi = (b * TT + t) * FF + f;
    float s = g_xh_acc[i]; g_xh_acc[i] = 0.f;
    float xh = s + histb[f];
    g_xhist[i] = xh;
    float mt = m[gi];
    g_xc[i] = mt * x[gi] + (1.f - mt) * xh;
    float dv = xh - tgt[gi];
    float tot = block_sum256(dv * dv * ev[gi]);
    if (threadIdx.x == 0) atomicAdd(&g_loss, tot / g_denom[t]);
}

// K3a: z partials = x_c @ feat_W^T (diag handled later), split-K 2x64
__global__ __launch_bounds__(256) void k3a(const float* __restrict__ featW) {
    int b0 = blockIdx.y * 64, j0 = blockIdx.x * 64, kb = blockIdx.z * 64;
    gemm_tile<64, 64>(64,
        [&](int r, int k) { return g_xc[(b0 + r) * FF + kb + k]; },
        [&](int r, int k) { return featW[(j0 + r) * FF + kb + k]; },
        [&](int r, int c, float acc) { atomicAdd(&g_z_acc[(b0 + r) * FF + j0 + c], acc); });
}

// K3b: z (subtract diagonal, +bias), c_h, c_c -> d_out, loss terms 2&3
__global__ void k3b(int t, const float* __restrict__ x, const float* __restrict__ m,
                    const float* __restrict__ featW, const float* __restrict__ featb,
                    const float* __restrict__ tgt, const float* __restrict__ ev,
                    float* __restrict__ out) {
    int i = blockIdx.x * 256 + threadIdx.x;
    int b = i >> 7, f = i & 127;
    int gi = (b * TT + t) * FF + f;
    float zacc = g_z_acc[i]; g_z_acc[i] = 0.f;
    float xc = g_xc[i];
    float z = zacc - xc * featW[f * FF + f] + featb[f];
    float a = g_alpha[gi];
    float xh = g_xhist[i];
    float ch = a * z + (1.f - a) * xh;
    float mt = m[gi];
    out[gi] = mt * x[gi] + (1.f - mt) * ch;     // imputation c_c
    float d1 = z - tgt[gi], d2 = ch - tgt[gi];
    float tot = block_sum256((d1 * d1 + d2 * d2) * ev[gi]);
    if (threadIdx.x == 0) atomicAdd(&g_loss, tot / g_denom[t]);
}

// K4: gates = [c_c, m] @ W_ih^T + h @ W_hh^T + b_ih + b_hh   (K = 768)
__global__ __launch_bounds__(256) void k4(int t, const float* __restrict__ m,
        const float* __restrict__ Wih, const float* __restrict__ Whh,
        const float* __restrict__ bih, const float* __restrict__ bhh,
        const float* __restrict__ cc /* = d_out */) {
    int b0 = blockIdx.y * 64, j0 = blockIdx.x * 32;
    gemm_tile<64, 32>(2 * FF + HH,
        [&](int r, int k) {
            int b = b0 + r;
            if (k < FF)        return cc[(b * TT + t) * FF + k];
            else if (k < 2*FF) return m[(b * TT + t) * FF + (k - FF)];
            else               return g_h[b * HH + (k - 2 * FF)];
        },
        [&](int r, int k) {
            int g = j0 + r;
            return (k < 2 * FF) ? Wih[g * (2 * FF) + k] : Whh[g * HH + (k - 2 * FF)];
        },
        [&](int r, int c, float acc) {
            int g = j0 + c;
            g_gates[(b0 + r) * (4 * HH) + g] = acc + bih[g] + bhh[g];
        });
}

// K5: LSTM cell update; fuse the NEXT step's gamma_h decay into the h write
__global__ void k5(int t) {
    int i = blockIdx.x * 256 + threadIdx.x;   // exactly BB*HH threads
    int b = i >> 9, j = i & 511;
    const float* gr = g_gates + b * (4 * HH);
    float ig = gr[j], fg = gr[HH + j], gg = gr[2 * HH + j], og = gr[3 * HH + j];
    float c = sigmoidf(fg) * g_c[i] + sigmoidf(ig) * tanhf(gg);
    float h = sigmoidf(og) * tanhf(c);
    g_c[i] = c;
    if (t + 1 < TT) h *= g_gh[(b * TT + (t + 1)) * HH + j];
    g_h[i] = h;
}

__global__ void k_final(float* out, int idx) {
    out[idx] = g_loss * (1.0f / TT);
}

// ---------------- launch ----------------
extern "C" void kernel_launch(void* const* d_in, const int* in_sizes, int n_in,
                              void* d_out, int out_size) {
    const float* x     = (const float*)d_in[0];
    const float* m     = (const float*)d_in[1];
    const float* d     = (const float*)d_in[2];
    const float* tgt   = (const float*)d_in[3];
    const float* ev    = (const float*)d_in[4];
    const float* tdhW  = (const float*)d_in[5];
    const float* tdhb  = (const float*)d_in[6];
    const float* tdxW  = (const float*)d_in[7];
    const float* tdxb  = (const float*)d_in[8];
    const float* histW = (const float*)d_in[9];
    const float* histb = (const float*)d_in[10];
    const float* featW = (const float*)d_in[11];
    const float* featb = (const float*)d_in[12];
    const float* wcW   = (const float*)d_in[13];
    const float* wcb   = (const float*)d_in[14];
    const float* Wih   = (const float*)d_in[15];
    const float* Whh   = (const float*)d_in[16];
    const float* bih   = (const float*)d_in[17];
    const float* bhh   = (const float*)d_in[18];
    float* out = (float*)d_out;

    k_init<<<(BB * HH) / 256, 256>>>();
    k_denom<<<TT, 256>>>(ev);
    k_gammax<<<(BT * FF) / 256, 256>>>(d, tdxW, tdxb);
    k_gammah<<<dim3(HH / 64, BT / 64), 256>>>(d, tdhW, tdhb);
    k_alpha<<<dim3(2 * FF / 128, BT / 64), 256>>>(m, wcW, wcb);   // (2, 512)

    for (int t = 0; t < TT; t++) {
        k2a<<<dim3(FF / 64, BB / 64, 4), 256>>>(histW);           // (2,4,4)
        k2b<<<(BB * FF) / 256, 256>>>(t, x, m, histb, tgt, ev);
        k3a<<<dim3(FF / 64, BB / 64, 2), 256>>>(featW);           // (2,4,2)
        k3b<<<(BB * FF) / 256, 256>>>(t, x, m, featW, featb, tgt, ev, out);
        k4<<<dim3(4 * HH / 32, BB / 64), 256>>>(t, m, Wih, Whh, bih, bhh, out); // (64,4)
        k5<<<(BB * HH) / 256, 256>>>(t);
    }

    int lossIdx = BB * TT * FF;
    if (out_size > lossIdx) k_final<<<1, 1>>>(out, lossIdx);
}